// round 5
// baseline (speedup 1.0000x reference)
#include <cuda_runtime.h>

// Problem constants
constexpr int NB   = 128;   // batch
constexpr int NT   = 128;   // encoder time steps
constexpr int NIN  = 3;     // input features
constexpr int NH   = 512;   // hidden
constexpr int NTGT = 32;    // decoder steps

constexpr int ENC_CTAS = 128;          // persistent grid, 1 CTA/SM co-resident
constexpr int DEC_CTAS = 128;
constexpr int SHW_STRIDE = 36;         // padded w row (floats)
constexpr int SHH_STRIDE = 516;        // padded h row (floats)
constexpr int SHW_FLOATS = NH * SHW_STRIDE;          // 18432
constexpr int SHH_FLOATS = 32 * SHH_STRIDE;          // 16512
constexpr int ENC_SMEM   = (SHW_FLOATS + SHH_FLOATS) * 4;  // 139776 bytes

// ---------------------------------------------------------------------------
// Static device scratch (allocation-free rule: __device__ globals)
// ---------------------------------------------------------------------------
__device__ float g_l0[NT * NB * (2 * NH)];      // encoder L0 concat outputs [t][b][1024]
__device__ float g_xs1[2 * NT * NB * NH];       // L1 input terms [d][t][b][512]
__device__ float g_h[2][2 * NB * NH];           // encoder state ping-pong
__device__ float g_dech[2][4 * NB * NH];        // decoder state ping-pong
__device__ unsigned g_cnt;                      // grid-barrier arrival counter (self-resetting)
__device__ unsigned g_gen;                      // grid-barrier generation (monotonic, replay-safe)

// ---------------------------------------------------------------------------
// Generation-based grid barrier. cnt returns to 0 after every barrier, gen
// only grows -> safe across any number of graph replays, no reset kernel.
// ---------------------------------------------------------------------------
__device__ __forceinline__ void grid_barrier(unsigned nctas)
{
    __threadfence();              // release this thread's stores to GPU scope
    __syncthreads();
    if (threadIdx.x == 0) {
        volatile unsigned* genp = &g_gen;
        unsigned gen = *genp;
        if (atomicAdd(&g_cnt, 1u) == nctas - 1) {
            g_cnt = 0;
            __threadfence();
            *genp = gen + 1;      // release
        } else {
            while (*genp == gen) { }
            __threadfence();      // acquire
        }
    }
    __syncthreads();
}

__global__ void nop_k() {}   // pad launches so ncu -s 5 -c 1 captures enc_persist

// ---------------------------------------------------------------------------
// Persistent encoder layer: all 128 time steps in ONE kernel.
// 128 CTAs = (16 j-tiles x 4 b-tiles x 2 dirs), 256 threads, tile 32b x 32j.
// Whh tile resident in smem (transposed); per step reload the 32x512 h tile
// (__ldcg, L2-coherent across the grid barrier) and run a sync-free FFMA loop
// with float4 h loads (4x fewer h wavefronts on the smem crossbar).
// ---------------------------------------------------------------------------
__global__ void __launch_bounds__(256) enc_persist(
    const float* __restrict__ x, const float* __restrict__ Wih0,
    const float* __restrict__ Whh_all, const float* __restrict__ bih,
    const float* __restrict__ bhh, int layer)
{
    extern __shared__ float sm[];
    float* sh_w = sm;                  // [NH][SHW_STRIDE] transposed weights
    float* sh_h = sm + SHW_FLOATS;     // [32][SHH_STRIDE] h tile

    const int blk = blockIdx.x;
    const int d   = blk >> 6;          // direction
    const int bt  = (blk >> 4) & 3;    // batch tile
    const int jt  = blk & 15;          // j tile
    const int b0  = bt * 32;
    const int j0  = jt * 32;
    const int tx  = threadIdx.x & 7;   // j group (4 j per thread)
    const int ty  = threadIdx.x >> 3;  // batch row within tile (0..31)
    const int b   = b0 + ty;
    const int j   = j0 + tx * 4;

    const float* Whh = Whh_all + d * NH * NH;

    // ---- one-time: load Whh tile transposed into smem ----
    {
        const int r  = threadIdx.x >> 3;        // 0..31 (j row)
        const int c0 = (threadIdx.x & 7) * 4;   // 0..28 (k col)
        for (int k0 = 0; k0 < NH; k0 += 32) {
            float4 w = *(const float4*)&Whh[(j0 + r) * NH + k0 + c0];
            sh_w[(k0 + c0 + 0) * SHW_STRIDE + r] = w.x;
            sh_w[(k0 + c0 + 1) * SHW_STRIDE + r] = w.y;
            sh_w[(k0 + c0 + 2) * SHW_STRIDE + r] = w.z;
            sh_w[(k0 + c0 + 3) * SHW_STRIDE + r] = w.w;
        }
    }

    // ---- per-thread constants in registers ----
    float bias0 = 0.f, bias1 = 0.f, bias2 = 0.f, bias3 = 0.f;
    float wi[12];
    if (layer == 0) {
        const int boff = d * NH + j;
        bias0 = bih[boff + 0] + bhh[boff + 0];
        bias1 = bih[boff + 1] + bhh[boff + 1];
        bias2 = bih[boff + 2] + bhh[boff + 2];
        bias3 = bih[boff + 3] + bhh[boff + 3];
        const float* wp = Wih0 + (d * NH + j) * NIN;
#pragma unroll
        for (int i = 0; i < 12; i++) wi[i] = wp[i];
    }
    __syncthreads();   // sh_w ready

    for (int t = 0; t < NT; t++) {
        const int td = d ? (NT - 1 - t) : t;

        // ---- load h_prev tile (skipped at t==0 since h0 == 0) ----
        if (t > 0) {
            const float* hprev = g_h[t & 1] + d * NB * NH;
            const int r  = threadIdx.x >> 3;
            const int c0 = (threadIdx.x & 7) * 4;
#pragma unroll
            for (int k0 = 0; k0 < NH; k0 += 32) {
                float4 hv = __ldcg((const float4*)&hprev[(b0 + r) * NH + k0 + c0]);
                *(float4*)&sh_h[r * SHH_STRIDE + k0 + c0] = hv;
            }
            __syncthreads();
        }

        // ---- accumulator init ----
        float a0, a1, a2, a3;
        if (layer == 0) {
            const float* xr = x + (b * NT + td) * NIN;
            const float x0 = xr[0], x1 = xr[1], x2 = xr[2];
            a0 = bias0 + x0 * wi[0] + x1 * wi[1]  + x2 * wi[2];
            a1 = bias1 + x0 * wi[3] + x1 * wi[4]  + x2 * wi[5];
            a2 = bias2 + x0 * wi[6] + x1 * wi[7]  + x2 * wi[8];
            a3 = bias3 + x0 * wi[9] + x1 * wi[10] + x2 * wi[11];
        } else {
            float4 xt = *(const float4*)&g_xs1[((d * NT + td) * NB + b) * NH + j];
            a0 = xt.x; a1 = xt.y; a2 = xt.z; a3 = xt.w;
        }

        // ---- recurrent GEMM: sync-free, weights resident, float4 h ----
        if (t > 0) {
            const float* hrow = &sh_h[ty * SHH_STRIDE];
            const float* wcol = &sh_w[tx * 4];
#pragma unroll 4
            for (int kk = 0; kk < NH; kk += 4) {
                float4 hv = *(const float4*)&hrow[kk];
                float4 w0 = *(const float4*)&wcol[(kk + 0) * SHW_STRIDE];
                float4 w1 = *(const float4*)&wcol[(kk + 1) * SHW_STRIDE];
                float4 w2 = *(const float4*)&wcol[(kk + 2) * SHW_STRIDE];
                float4 w3 = *(const float4*)&wcol[(kk + 3) * SHW_STRIDE];
                a0 += hv.x * w0.x; a1 += hv.x * w0.y; a2 += hv.x * w0.z; a3 += hv.x * w0.w;
                a0 += hv.y * w1.x; a1 += hv.y * w1.y; a2 += hv.y * w1.z; a3 += hv.y * w1.w;
                a0 += hv.z * w2.x; a1 += hv.z * w2.y; a2 += hv.z * w2.z; a3 += hv.z * w2.w;
                a0 += hv.w * w3.x; a1 += hv.w * w3.y; a2 += hv.w * w3.z; a3 += hv.w * w3.w;
            }
        }

        // ---- activation + writes ----
        float4 r4 = make_float4(tanhf(a0), tanhf(a1), tanhf(a2), tanhf(a3));
        float* hnext = g_h[(t + 1) & 1] + d * NB * NH;
        *(float4*)&hnext[b * NH + j] = r4;
        if (layer == 0)
            *(float4*)&g_l0[(td * NB + b) * (2 * NH) + d * NH + j] = r4;
        if (t == NT - 1)
            *(float4*)&g_dech[0][(((layer ? 2 : 0) + d) * NB + b) * NH + j] = r4;

        if (t < NT - 1)
            grid_barrier(ENC_CTAS);
    }
}

// ---------------------------------------------------------------------------
// Big GEMM: xs1[d][t][b][j] = l0[t][b][:] . Wih1[d][j][:] + bih1 + bhh1
// M = 16384, N = 512, K = 1024. Tile 64x64, 256 threads, 4x4 per thread.
// ---------------------------------------------------------------------------
__global__ void __launch_bounds__(256) xs1_gemm(
    const float* __restrict__ Wih1, const float* __restrict__ bih,
    const float* __restrict__ bhh)
{
    __shared__ __align__(16) float sh_a[64][36];
    __shared__ __align__(16) float sh_w[32][68];

    const int d  = blockIdx.z;
    const int j0 = blockIdx.x * 64;
    const int m0 = blockIdx.y * 64;
    const int tx = threadIdx.x & 15;
    const int ty = threadIdx.x >> 4;
    const int lr = threadIdx.x >> 3;
    const int lk = (threadIdx.x & 7) * 4;

    const float* Wd = Wih1 + d * NH * (2 * NH);
    float acc[4][4] = {};

    for (int k0 = 0; k0 < 2 * NH; k0 += 32) {
        *(float4*)&sh_a[lr][lk]      = *(const float4*)&g_l0[(m0 + lr) * (2 * NH) + k0 + lk];
        *(float4*)&sh_a[lr + 32][lk] = *(const float4*)&g_l0[(m0 + lr + 32) * (2 * NH) + k0 + lk];
        float4 w0 = *(const float4*)&Wd[(j0 + lr) * (2 * NH) + k0 + lk];
        float4 w1 = *(const float4*)&Wd[(j0 + lr + 32) * (2 * NH) + k0 + lk];
        sh_w[lk + 0][lr] = w0.x; sh_w[lk + 1][lr] = w0.y;
        sh_w[lk + 2][lr] = w0.z; sh_w[lk + 3][lr] = w0.w;
        sh_w[lk + 0][lr + 32] = w1.x; sh_w[lk + 1][lr + 32] = w1.y;
        sh_w[lk + 2][lr + 32] = w1.z; sh_w[lk + 3][lr + 32] = w1.w;
        __syncthreads();
#pragma unroll
        for (int kk = 0; kk < 32; kk++) {
            float4 wv = *(float4*)&sh_w[kk][tx * 4];
            float  v0 = sh_a[ty * 4 + 0][kk];
            float  v1 = sh_a[ty * 4 + 1][kk];
            float  v2 = sh_a[ty * 4 + 2][kk];
            float  v3 = sh_a[ty * 4 + 3][kk];
            acc[0][0] += v0 * wv.x; acc[0][1] += v0 * wv.y; acc[0][2] += v0 * wv.z; acc[0][3] += v0 * wv.w;
            acc[1][0] += v1 * wv.x; acc[1][1] += v1 * wv.y; acc[1][2] += v1 * wv.z; acc[1][3] += v1 * wv.w;
            acc[2][0] += v2 * wv.x; acc[2][1] += v2 * wv.y; acc[2][2] += v2 * wv.z; acc[2][3] += v2 * wv.w;
            acc[3][0] += v3 * wv.x; acc[3][1] += v3 * wv.y; acc[3][2] += v3 * wv.z; acc[3][3] += v3 * wv.w;
        }
        __syncthreads();
    }

    const int jj = j0 + tx * 4;
    const float b0v = bih[(2 + d) * NH + jj + 0] + bhh[(2 + d) * NH + jj + 0];
    const float b1v = bih[(2 + d) * NH + jj + 1] + bhh[(2 + d) * NH + jj + 1];
    const float b2v = bih[(2 + d) * NH + jj + 2] + bhh[(2 + d) * NH + jj + 2];
    const float b3v = bih[(2 + d) * NH + jj + 3] + bhh[(2 + d) * NH + jj + 3];
#pragma unroll
    for (int i = 0; i < 4; i++) {
        const int m = m0 + ty * 4 + i;
        float4 r = make_float4(acc[i][0] + b0v, acc[i][1] + b1v,
                               acc[i][2] + b2v, acc[i][3] + b3v);
        *(float4*)&g_xs1[(d * NT * NB + m) * NH + jj] = r;
    }
}

// ---------------------------------------------------------------------------
// Persistent decoder: all 32 steps x 4 layers + output/feedback in ONE kernel.
// 128 CTAs = (16 j-tiles x 8 b-tiles), 256 threads, tile 16b x 32j,
// 2 outputs/thread. Grid barrier between layer phases (128 total).
// Output dot + feedback folded into the top of each step (smem-resident decin).
// ---------------------------------------------------------------------------
__device__ __forceinline__ void dec_gemm512(
    const float* __restrict__ A, const float* __restrict__ W,
    int b0, int j0, int tx, int ty, float& a0, float& a1,
    float (*sh_h)[36], float (*sh_w)[36])
{
    const int wr = threadIdx.x >> 3;        // 0..31 (j row)
    const int wc = (threadIdx.x & 7) * 4;   // 0..28 (k col)
    for (int k0 = 0; k0 < NH; k0 += 32) {
        float4 w4 = __ldg((const float4*)&W[(j0 + wr) * NH + k0 + wc]);
        sh_w[wc + 0][wr] = w4.x; sh_w[wc + 1][wr] = w4.y;
        sh_w[wc + 2][wr] = w4.z; sh_w[wc + 3][wr] = w4.w;
        if (threadIdx.x < 128) {
            const int hr = threadIdx.x >> 3;        // 0..15
            const int hc = (threadIdx.x & 7) * 4;
            *(float4*)&sh_h[hr][hc] =
                __ldcg((const float4*)&A[(b0 + hr) * NH + k0 + hc]);
        }
        __syncthreads();
#pragma unroll
        for (int kk = 0; kk < 32; kk += 4) {
            float4 hv = *(const float4*)&sh_h[ty][kk];
            float2 w0 = *(const float2*)&sh_w[kk + 0][tx * 2];
            float2 w1 = *(const float2*)&sh_w[kk + 1][tx * 2];
            float2 w2 = *(const float2*)&sh_w[kk + 2][tx * 2];
            float2 w3 = *(const float2*)&sh_w[kk + 3][tx * 2];
            a0 += hv.x * w0.x; a1 += hv.x * w0.y;
            a0 += hv.y * w1.x; a1 += hv.y * w1.y;
            a0 += hv.z * w2.x; a1 += hv.z * w2.y;
            a0 += hv.w * w3.x; a1 += hv.w * w3.y;
        }
        __syncthreads();
    }
}

__global__ void __launch_bounds__(256) dec_persist(
    const float* __restrict__ x,    const float* __restrict__ Wih0,
    const float* __restrict__ Wihr, const float* __restrict__ Whh,
    const float* __restrict__ bih,  const float* __restrict__ bhh,
    const float* __restrict__ linW, const float* __restrict__ linb,
    float* __restrict__ out)
{
    __shared__ __align__(16) float sh_h[16][36];
    __shared__ __align__(16) float sh_w[32][36];
    __shared__ float s_dec[16][3];   // decin for this CTA's b-tile (persists across steps)
    __shared__ float s_o0[16];

    const int jt = blockIdx.x & 15;
    const int bt = blockIdx.x >> 4;
    const int j0 = jt * 32;
    const int b0 = bt * 16;
    const int tx = threadIdx.x & 15;     // j pair
    const int ty = threadIdx.x >> 4;     // batch row (0..15)
    const int b  = b0 + ty;
    const int j  = j0 + tx * 2;
    const int wid  = threadIdx.x >> 5;
    const int lane = threadIdx.x & 31;

    // initial decin = x[:, -1, :]
    if (threadIdx.x < 16) {
        const float* xr = x + ((b0 + threadIdx.x) * NT + (NT - 1)) * NIN;
        s_dec[threadIdx.x][0] = xr[0];
        s_dec[threadIdx.x][1] = xr[1];
        s_dec[threadIdx.x][2] = xr[2];
    }
    __syncthreads();

    for (int t = 0; t < NTGT; t++) {
        const int p = t & 1;

        // ---- fold output dot of step t-1 + feedback update ----
        if (t > 0) {
            const float* h3 = g_dech[p] + 3 * NB * NH;   // h3 @ t-1
#pragma unroll
            for (int r = 0; r < 2; r++) {
                const int br = 2 * wid + r;
                const float* row = h3 + (b0 + br) * NH;
                float s = 0.f;
                for (int i = lane; i < NH; i += 32)
                    s += __ldcg(&row[i]) * linW[i];
#pragma unroll
                for (int o = 16; o; o >>= 1) s += __shfl_xor_sync(0xffffffffu, s, o);
                if (lane == 0) s_o0[br] = s;
            }
            __syncthreads();
            if (threadIdx.x < 16) {
                float o0 = s_o0[threadIdx.x] + linb[0];
                if (jt == 0) out[(b0 + threadIdx.x) * NTGT + (t - 1)] = o0;
                float s1 = s_dec[threadIdx.x][0] - o0;
                float s2 = s_dec[threadIdx.x][1] - s1;
                s_dec[threadIdx.x][0] = o0;
                s_dec[threadIdx.x][1] = s1;
                s_dec[threadIdx.x][2] = s2;
            }
            __syncthreads();
        }

        // ---- 4 layers, grid barrier between phases ----
        for (int l = 0; l < 4; l++) {
            float a0 = bih[l * NH + j + 0] + bhh[l * NH + j + 0];
            float a1 = bih[l * NH + j + 1] + bhh[l * NH + j + 1];

            if (l == 0) {
                const float i0 = s_dec[ty][0], i1 = s_dec[ty][1], i2 = s_dec[ty][2];
                const float* wp = Wih0 + j * NIN;
                a0 += i0 * wp[0] + i1 * wp[1] + i2 * wp[2];
                a1 += i0 * wp[3] + i1 * wp[4] + i2 * wp[5];
            }

            dec_gemm512(g_dech[p] + l * NB * NH, Whh + l * NH * NH,
                        b0, j0, tx, ty, a0, a1, sh_h, sh_w);
            if (l > 0)
                dec_gemm512(g_dech[1 - p] + (l - 1) * NB * NH,
                            Wihr + (l - 1) * NH * NH,
                            b0, j0, tx, ty, a0, a1, sh_h, sh_w);

            float* hout = g_dech[1 - p] + l * NB * NH;
            float2 r2 = make_float2(tanhf(a0), tanhf(a1));
            *(float2*)&hout[b * NH + j] = r2;

            grid_barrier(DEC_CTAS);
        }
    }

    // ---- final output (t = NTGT-1): h3 @ 31 lives in g_dech[0] ----
    {
        const float* h3 = g_dech[0] + 3 * NB * NH;
#pragma unroll
        for (int r = 0; r < 2; r++) {
            const int br = 2 * wid + r;
            const float* row = h3 + (b0 + br) * NH;
            float s = 0.f;
            for (int i = lane; i < NH; i += 32)
                s += __ldcg(&row[i]) * linW[i];
#pragma unroll
            for (int o = 16; o; o >>= 1) s += __shfl_xor_sync(0xffffffffu, s, o);
            if (lane == 0) s_o0[br] = s;
        }
        __syncthreads();
        if (threadIdx.x < 16 && jt == 0)
            out[(b0 + threadIdx.x) * NTGT + (NTGT - 1)] = s_o0[threadIdx.x] + linb[0];
    }
}

// ---------------------------------------------------------------------------
// Launch sequence (graph-capturable: kernel launches only)
// ---------------------------------------------------------------------------
extern "C" void kernel_launch(void* const* d_in, const int* in_sizes, int n_in,
                              void* d_out, int out_size)
{
    const float* x        = (const float*)d_in[0];
    const float* enc_Wih0 = (const float*)d_in[2];
    const float* enc_Whh0 = (const float*)d_in[3];
    const float* enc_Wih1 = (const float*)d_in[4];
    const float* enc_Whh1 = (const float*)d_in[5];
    const float* enc_bih  = (const float*)d_in[6];
    const float* enc_bhh  = (const float*)d_in[7];
    const float* dec_Wih0 = (const float*)d_in[8];
    const float* dec_Wihr = (const float*)d_in[9];
    const float* dec_Whh  = (const float*)d_in[10];
    const float* dec_bih  = (const float*)d_in[11];
    const float* dec_bhh  = (const float*)d_in[12];
    const float* lin_W    = (const float*)d_in[13];
    const float* lin_b    = (const float*)d_in[14];
    float* out = (float*)d_out;

    cudaFuncSetAttribute(enc_persist, cudaFuncAttributeMaxDynamicSharedMemorySize,
                         ENC_SMEM);

    // pad launches so ncu (-s 5 -c 1) profiles enc_persist layer 0
    for (int i = 0; i < 5; i++) nop_k<<<1, 1>>>();

    // Encoder layer 0: persistent, all 128 steps
    enc_persist<<<ENC_CTAS, 256, ENC_SMEM>>>(x, enc_Wih0, enc_Whh0,
                                             enc_bih, enc_bhh, 0);

    // Layer-1 input terms for all t (both dirs), biases folded in
    xs1_gemm<<<dim3(8, 256, 2), 256>>>(enc_Wih1, enc_bih, enc_bhh);

    // Encoder layer 1: persistent
    enc_persist<<<ENC_CTAS, 256, ENC_SMEM>>>(x, enc_Wih0, enc_Whh1,
                                             enc_bih, enc_bhh, 1);

    // Decoder: persistent, all 32 steps x 4 layers + output/feedback
    dec_persist<<<DEC_CTAS, 256>>>(x, dec_Wih0, dec_Wihr, dec_Whh,
                                   dec_bih, dec_bhh, lin_W, lin_b, out);
}